// round 4
// baseline (speedup 1.0000x reference)
#include <cuda_runtime.h>
#include <cstdint>

#define NROWS 32768      // B*T
#define DIM   1536       // L*IN
#define EDIM  1024       // embedding size == H1 == H2
#define ODIM  512

// Scratch (allocation-free: __device__ globals).
// g_gh doubles as: gated input [NROWS,DIM], then (after GEMM1 consumes it)
// layer-2 activation buffer [NROWS,EDIM] (128MB < 192MB).
__device__ float g_gh  [(size_t)NROWS * DIM];    // 192 MB
__device__ float g_bufA[(size_t)NROWS * EDIM];   // 128 MB
__device__ float g_WeT [(size_t)EDIM * DIM];     // 6 MB
__device__ float g_bsum[EDIM];

__device__ __forceinline__ uint32_t f2tf32(float f) {
    uint32_t u;
    asm("cvt.rna.tf32.f32 %0, %1;" : "=r"(u) : "f"(f));
    return u;
}

__device__ __forceinline__ void mma_tf32(float* c, const uint32_t* a, const uint32_t* b) {
    asm("mma.sync.aligned.m16n8k8.row.col.f32.tf32.tf32.f32 "
        "{%0,%1,%2,%3},{%4,%5,%6,%7},{%8,%9},{%0,%1,%2,%3};"
        : "+f"(c[0]), "+f"(c[1]), "+f"(c[2]), "+f"(c[3])
        : "r"(a[0]), "r"(a[1]), "r"(a[2]), "r"(a[3]),
          "r"(b[0]), "r"(b[1]));
}

// Buffer selector resolved in DEVICE code (no cudaGetSymbolAddress on host).
// 0 = g_gh, 1 = g_bufA, else = external pointer.
__device__ __forceinline__ float* selbuf(int s, float* ext) {
    if (s == 0) return g_gh;
    if (s == 1) return g_bufA;
    return ext;
}

// ---------------------------------------------------------------------------
// Weight prep: WeT[e, l*512+i] = We[l, e, i];  bsum[e] = sum_l be[l, e]
// ---------------------------------------------------------------------------
__global__ void prep_kernel(const float* __restrict__ We, const float* __restrict__ be) {
    int idx = blockIdx.x * 256 + threadIdx.x;
    if (idx < EDIM * DIM) {
        int e = idx / DIM, k = idx - e * DIM;
        int l = k >> 9, i = k & 511;
        g_WeT[idx] = We[((size_t)l * EDIM + e) * 512 + i];
    }
    if (idx < EDIM) g_bsum[idx] = be[idx] + be[EDIM + idx] + be[2 * EDIM + idx];
}

// ---------------------------------------------------------------------------
// Gates: g[n,l] = sigmoid(dot(x[n,:], Wg[l,:])), gh[n,k] = x[n,k] * g[n, k/512]
// One 128-thread block per row.
// ---------------------------------------------------------------------------
__global__ void gate_kernel(const float* __restrict__ x, const float* __restrict__ Wgt) {
    int n = blockIdx.x;
    int tid = threadIdx.x;
    const float* xr = x + (size_t)n * DIM;
    float xv[12];
    float a0 = 0.f, a1 = 0.f, a2 = 0.f;
#pragma unroll
    for (int j = 0; j < 12; j++) {
        int k = tid + j * 128;
        float v = xr[k];
        xv[j] = v;
        a0 += v * Wgt[k];
        a1 += v * Wgt[DIM + k];
        a2 += v * Wgt[2 * DIM + k];
    }
#pragma unroll
    for (int o = 16; o > 0; o >>= 1) {
        a0 += __shfl_down_sync(0xffffffffu, a0, o);
        a1 += __shfl_down_sync(0xffffffffu, a1, o);
        a2 += __shfl_down_sync(0xffffffffu, a2, o);
    }
    __shared__ float red[3][4];
    __shared__ float gs[3];
    int lane = tid & 31, wid = tid >> 5;
    if (lane == 0) { red[0][wid] = a0; red[1][wid] = a1; red[2][wid] = a2; }
    __syncthreads();
    if (tid < 3) {
        float s = red[tid][0] + red[tid][1] + red[tid][2] + red[tid][3];
        gs[tid] = 1.f / (1.f + expf(-s));
    }
    __syncthreads();
    float g0 = gs[0], g1 = gs[1], g2 = gs[2];
    float* o = g_gh + (size_t)n * DIM;
#pragma unroll
    for (int j = 0; j < 12; j++) {
        int k = tid + j * 128;
        float gl = (j < 4) ? g0 : ((j < 8) ? g1 : g2);
        o[k] = xv[j] * gl;
    }
}

// ---------------------------------------------------------------------------
// TF32 GEMM: C[m,n] = act( sum_k A[m,k] * W[n,k] + bias[n] )   (A @ W^T)
// Block tile 128x128, K-tile 16, 8 warps (2 x 4), warp tile 64x32.
// ACT: 0 = none, 1 = relu, 2 = tanh.  WSEL: 0 = W from g_WeT, 1 = external.
// aSel/cSel pick device-global scratch or external pointers.
// ---------------------------------------------------------------------------
constexpr int LDS_ = 20;  // row stride in 32-bit words (16 + 4 pad -> conflict-free)

template <int ACT, int WSEL>
__global__ void __launch_bounds__(256) gemm_tf32_kernel(
    const float* __restrict__ Aext, const float* __restrict__ Wext,
    const float* __restrict__ biasE, float* __restrict__ Cext,
    int aSel, int cSel, int Nn, int K) {
    __shared__ uint32_t sA[2][128 * LDS_];
    __shared__ uint32_t sB[2][128 * LDS_];

    const float* A = selbuf(aSel, (float*)Aext);
    float* C = selbuf(cSel, Cext);
    const float* W = (WSEL == 0) ? g_WeT : Wext;
    const float* bias = (WSEL == 0) ? g_bsum : biasE;

    int tid = threadIdx.x;
    int lane = tid & 31, warp = tid >> 5;
    int wm = warp & 1, wn = warp >> 1;   // 2 warps along M (64 rows), 4 along N (32 cols)
    int mW = wm * 64, nW = wn * 32;
    int r = lane >> 2, cc = lane & 3;

    const float* Ag = A + (size_t)blockIdx.y * 128 * K;
    const float* Wp = W + (size_t)blockIdx.x * 128 * K;

    float acc[4][4][4];
#pragma unroll
    for (int i = 0; i < 4; i++)
#pragma unroll
        for (int j = 0; j < 4; j++)
#pragma unroll
            for (int k = 0; k < 4; k++) acc[i][j][k] = 0.f;

    int row0 = tid >> 2;            // 0..63
    int row1 = row0 + 64;           // 64..127
    int k4 = (tid & 3) << 2;        // 0,4,8,12

    float4 ra0, ra1, rb0, rb1;
    auto ldg_tile = [&](int t) {
        size_t ko = (size_t)t * 16 + k4;
        ra0 = *(const float4*)&Ag[(size_t)row0 * K + ko];
        ra1 = *(const float4*)&Ag[(size_t)row1 * K + ko];
        rb0 = *(const float4*)&Wp[(size_t)row0 * K + ko];
        rb1 = *(const float4*)&Wp[(size_t)row1 * K + ko];
    };
    auto sts_tile = [&](int buf) {
        uint4 u;
        u.x = f2tf32(ra0.x); u.y = f2tf32(ra0.y); u.z = f2tf32(ra0.z); u.w = f2tf32(ra0.w);
        *(uint4*)&sA[buf][row0 * LDS_ + k4] = u;
        u.x = f2tf32(ra1.x); u.y = f2tf32(ra1.y); u.z = f2tf32(ra1.z); u.w = f2tf32(ra1.w);
        *(uint4*)&sA[buf][row1 * LDS_ + k4] = u;
        u.x = f2tf32(rb0.x); u.y = f2tf32(rb0.y); u.z = f2tf32(rb0.z); u.w = f2tf32(rb0.w);
        *(uint4*)&sB[buf][row0 * LDS_ + k4] = u;
        u.x = f2tf32(rb1.x); u.y = f2tf32(rb1.y); u.z = f2tf32(rb1.z); u.w = f2tf32(rb1.w);
        *(uint4*)&sB[buf][row1 * LDS_ + k4] = u;
    };

    ldg_tile(0);
    sts_tile(0);
    __syncthreads();

    int tiles = K >> 4;
    for (int t = 0; t < tiles; ++t) {
        int buf = t & 1;
        if (t + 1 < tiles) ldg_tile(t + 1);

#pragma unroll
        for (int ks = 0; ks < 2; ks++) {
            uint32_t af[4][4], bf[4][2];
#pragma unroll
            for (int mt = 0; mt < 4; mt++) {
                const uint32_t* p = &sA[buf][(mW + mt * 16 + r) * LDS_ + ks * 8 + cc];
                af[mt][0] = p[0];
                af[mt][1] = p[8 * LDS_];
                af[mt][2] = p[4];
                af[mt][3] = p[8 * LDS_ + 4];
            }
#pragma unroll
            for (int nt = 0; nt < 4; nt++) {
                const uint32_t* q = &sB[buf][(nW + nt * 8 + r) * LDS_ + ks * 8 + cc];
                bf[nt][0] = q[0];
                bf[nt][1] = q[4];
            }
#pragma unroll
            for (int mt = 0; mt < 4; mt++)
#pragma unroll
                for (int nt = 0; nt < 4; nt++)
                    mma_tf32(acc[mt][nt], af[mt], bf[nt]);
        }

        if (t + 1 < tiles) {
            sts_tile(buf ^ 1);
            __syncthreads();
        }
    }

    // Epilogue: bias + activation + fp32 store
    int gm = blockIdx.y * 128 + mW;
    int gn = blockIdx.x * 128 + nW;
#pragma unroll
    for (int mt = 0; mt < 4; mt++) {
        int r0 = gm + mt * 16 + r;
#pragma unroll
        for (int nt = 0; nt < 4; nt++) {
            int c0 = gn + nt * 8 + 2 * cc;
            float b0 = bias[c0], b1v = bias[c0 + 1];
            float v0 = acc[mt][nt][0] + b0;
            float v1 = acc[mt][nt][1] + b1v;
            float v2 = acc[mt][nt][2] + b0;
            float v3 = acc[mt][nt][3] + b1v;
            if (ACT == 1) {
                v0 = fmaxf(v0, 0.f); v1 = fmaxf(v1, 0.f);
                v2 = fmaxf(v2, 0.f); v3 = fmaxf(v3, 0.f);
            } else if (ACT == 2) {
                v0 = tanhf(v0); v1 = tanhf(v1);
                v2 = tanhf(v2); v3 = tanhf(v3);
            }
            *(float2*)&C[(size_t)r0 * Nn + c0] = make_float2(v0, v1);
            *(float2*)&C[(size_t)(r0 + 8) * Nn + c0] = make_float2(v2, v3);
        }
    }
}

// ---------------------------------------------------------------------------
extern "C" void kernel_launch(void* const* d_in, const int* in_sizes, int n_in,
                              void* d_out, int out_size) {
    const float* x  = (const float*)d_in[0];
    const float* Wg = (const float*)d_in[1];
    const float* We = (const float*)d_in[2];
    const float* be = (const float*)d_in[3];
    const float* W1 = (const float*)d_in[4];
    const float* b1 = (const float*)d_in[5];
    const float* W2 = (const float*)d_in[6];
    const float* b2 = (const float*)d_in[7];
    const float* Wo = (const float*)d_in[8];
    const float* bo = (const float*)d_in[9];
    float* out = (float*)d_out;

    // Pure kernel launches — nothing else touches the stream during capture.
    prep_kernel<<<(EDIM * DIM + 255) / 256, 256>>>(We, be);
    gate_kernel<<<NROWS, 128>>>(x, Wg);

    // he  = relu(gh @ WeT^T + bsum)        : A = g_gh(0)   -> C = g_bufA(1)
    gemm_tf32_kernel<1, 0><<<dim3(EDIM / 128, NROWS / 128), 256>>>(
        nullptr, nullptr, nullptr, nullptr, 0, 1, EDIM, DIM);
    // o1  = tanh(he @ W1^T + b1)           : A = g_bufA(1) -> C = g_gh(0) (reuse)
    gemm_tf32_kernel<2, 1><<<dim3(EDIM / 128, NROWS / 128), 256>>>(
        nullptr, W1, b1, nullptr, 1, 0, EDIM, EDIM);
    // o2  = tanh(o1 @ W2^T + b2)           : A = g_gh(0)   -> C = g_bufA(1)
    gemm_tf32_kernel<2, 1><<<dim3(EDIM / 128, NROWS / 128), 256>>>(
        nullptr, W2, b2, nullptr, 0, 1, EDIM, EDIM);
    // out = o2 @ Wo^T + bo                 : A = g_bufA(1) -> C = out (external)
    gemm_tf32_kernel<0, 1><<<dim3(ODIM / 128, NROWS / 128), 256>>>(
        nullptr, Wo, bo, out, 1, 2, ODIM, EDIM);
}

// round 7
// speedup vs baseline: 1.1136x; 1.1136x over previous
#include <cuda_runtime.h>
#include <cstdint>

#define NROWS 32768      // B*T
#define DIM   1536       // L*IN
#define EDIM  1024
#define ODIM  512

// GEMM tiling
#define BM 256
#define BN 128
#define KT 16
#define LDSW 20                        // padded row stride in words (conflict-free)
#define ASTAGE (BM * LDSW * 4)         // 20480 B
#define BSTAGE (BN * LDSW * 4)         // 10240 B
#define STG (ASTAGE + BSTAGE)          // 30720 B
#define NSTAGES 3
#define SMEM_DYN (NSTAGES * STG)       // 92160 B

// ---------------- device-global scratch (no allocs) ----------------
__device__ float g_gh  [(size_t)NROWS * DIM];    // gated input; reused as o1 buffer
__device__ float g_bufA[(size_t)NROWS * EDIM];
__device__ float g_WeT [(size_t)EDIM * DIM];     // tf32-rounded transposed We
__device__ float g_W1r [(size_t)EDIM * EDIM];
__device__ float g_W2r [(size_t)EDIM * EDIM];
__device__ float g_Wor [(size_t)ODIM * EDIM];
__device__ float g_bsum[EDIM];

// ---------------- helpers ----------------
__device__ __forceinline__ uint32_t f2tf32(float f) {
    uint32_t u;
    asm("cvt.rna.tf32.f32 %0, %1;" : "=r"(u) : "f"(f));
    return u;
}
__device__ __forceinline__ float rtf(float f) { return __uint_as_float(f2tf32(f)); }

__device__ __forceinline__ uint32_t smem_u32(const void* p) {
    uint32_t a;
    asm("{ .reg .u64 t; cvta.to.shared.u64 t, %1; cvt.u32.u64 %0, t; }" : "=r"(a) : "l"(p));
    return a;
}
__device__ __forceinline__ void cp16(uint32_t dst, const void* src) {
    asm volatile("cp.async.cg.shared.global [%0], [%1], 16;" :: "r"(dst), "l"(src));
}
__device__ __forceinline__ void cp_commit() { asm volatile("cp.async.commit_group;" ::: "memory"); }
__device__ __forceinline__ void cp_wait1()  { asm volatile("cp.async.wait_group 1;" ::: "memory"); }

__device__ __forceinline__ void mma_tf32(float* c, const uint32_t* a, const uint32_t* b) {
    asm("mma.sync.aligned.m16n8k8.row.col.f32.tf32.tf32.f32 "
        "{%0,%1,%2,%3},{%4,%5,%6,%7},{%8,%9},{%0,%1,%2,%3};"
        : "+f"(c[0]), "+f"(c[1]), "+f"(c[2]), "+f"(c[3])
        : "r"(a[0]), "r"(a[1]), "r"(a[2]), "r"(a[3]),
          "r"(b[0]), "r"(b[1]));
}

// ---------------------------------------------------------------------------
// prep: WeT (tf32-rounded, transposed), rounded W copies, bias sum (fp32)
// ---------------------------------------------------------------------------
__global__ void prep_kernel(const float* __restrict__ We, const float* __restrict__ be,
                            const float* __restrict__ W1, const float* __restrict__ W2,
                            const float* __restrict__ Wo) {
    int idx = blockIdx.x * 256 + threadIdx.x;
    if (idx < EDIM * DIM) {
        int e = idx / DIM, k = idx - e * DIM;
        int l = k >> 9, i = k & 511;
        g_WeT[idx] = rtf(We[((size_t)l * EDIM + e) * 512 + i]);
    }
    if (idx < EDIM * EDIM) {
        g_W1r[idx] = rtf(W1[idx]);
        g_W2r[idx] = rtf(W2[idx]);
    }
    if (idx < ODIM * EDIM) g_Wor[idx] = rtf(Wo[idx]);
    if (idx < EDIM) g_bsum[idx] = be[idx] + be[EDIM + idx] + be[2 * EDIM + idx];
}

// ---------------------------------------------------------------------------
// gates: g[n,l] = sigmoid(x[n,:].Wg[l,:]); gh[n,k] = rtf(x[n,k]*g[n,k/512])
// ---------------------------------------------------------------------------
__global__ void gate_kernel(const float* __restrict__ x, const float* __restrict__ Wgt) {
    int n = blockIdx.x;
    int tid = threadIdx.x;
    const float* xr = x + (size_t)n * DIM;
    float xv[12];
    float a0 = 0.f, a1 = 0.f, a2 = 0.f;
#pragma unroll
    for (int j = 0; j < 12; j++) {
        int k = tid + j * 128;
        float v = xr[k];
        xv[j] = v;
        a0 += v * Wgt[k];
        a1 += v * Wgt[DIM + k];
        a2 += v * Wgt[2 * DIM + k];
    }
#pragma unroll
    for (int o = 16; o > 0; o >>= 1) {
        a0 += __shfl_down_sync(0xffffffffu, a0, o);
        a1 += __shfl_down_sync(0xffffffffu, a1, o);
        a2 += __shfl_down_sync(0xffffffffu, a2, o);
    }
    __shared__ float red[3][4];
    __shared__ float gs[3];
    int lane = tid & 31, wid = tid >> 5;
    if (lane == 0) { red[0][wid] = a0; red[1][wid] = a1; red[2][wid] = a2; }
    __syncthreads();
    if (tid < 3) {
        float s = red[tid][0] + red[tid][1] + red[tid][2] + red[tid][3];
        gs[tid] = 1.f / (1.f + expf(-s));
    }
    __syncthreads();
    float g0 = gs[0], g1 = gs[1], g2 = gs[2];
    float* o = g_gh + (size_t)n * DIM;
#pragma unroll
    for (int j = 0; j < 12; j++) {
        int k = tid + j * 128;
        float gl = (j < 4) ? g0 : ((j < 8) ? g1 : g2);
        o[k] = rtf(xv[j] * gl);
    }
}

// ---------------------------------------------------------------------------
// TF32 GEMM (legacy mma.sync): C = act(A @ W^T + bias)
// Block tile 256x128, warp tile 64x64 (8 warps, 4Mx2N), K-tile 16,
// 3-stage cp.async pipeline. Inputs must be pre-rounded tf32.
// ACT: 0 none, 1 relu+round, 2 tanh+round.
// ---------------------------------------------------------------------------
template <int ACT>
__global__ void __launch_bounds__(256) gemm_tf32_big(
    const float* __restrict__ biasE, float* __restrict__ Cext,
    int aSel, int wSel, int cSel, int Nn, int K) {
    extern __shared__ char smem[];
    uint32_t sb = smem_u32(smem);

    const float* A = (aSel == 0) ? g_gh : g_bufA;
    const float* W = (wSel == 0) ? g_WeT : (wSel == 1) ? g_W1r : (wSel == 2) ? g_W2r : g_Wor;
    const float* bias = (wSel == 0) ? g_bsum : biasE;
    float* C = (cSel == 0) ? g_gh : (cSel == 1) ? g_bufA : Cext;

    int tid = threadIdx.x;
    int lane = tid & 31, warp = tid >> 5;
    int wm = warp & 3, wn = warp >> 2;    // 4 warps along M, 2 along N
    int mW = wm * 64, nW = wn * 64;
    int r = lane >> 2, cc = lane & 3;

    int mBase = blockIdx.y * BM;
    int nBase = blockIdx.x * BN;
    const float* Ag = A + (size_t)mBase * K;
    const float* Wg = W + (size_t)nBase * K;

    // per-thread cp.async assignment (16B chunks)
    int arow = tid >> 2;              // base A row for j-chunks (stride 64 rows)
    int c4 = (tid & 3) * 4;           // k word offset 0/4/8/12

    auto load_stage = [&](int kt, int s) {
        uint32_t ab = sb + (uint32_t)s * STG;
        uint32_t bb = ab + ASTAGE;
        size_t ko = (size_t)kt * KT + c4;
#pragma unroll
        for (int j = 0; j < 4; j++) {
            int row = arow + j * 64;
            cp16(ab + (uint32_t)(row * LDSW + c4) * 4, Ag + (size_t)row * K + ko);
        }
#pragma unroll
        for (int j = 0; j < 2; j++) {
            int row = arow + j * 64;
            cp16(bb + (uint32_t)(row * LDSW + c4) * 4, Wg + (size_t)row * K + ko);
        }
    };

    float acc[4][8][4];
#pragma unroll
    for (int i = 0; i < 4; i++)
#pragma unroll
        for (int j = 0; j < 8; j++)
#pragma unroll
            for (int k = 0; k < 4; k++) acc[i][j][k] = 0.f;

    int T = K / KT;
    load_stage(0, 0); cp_commit();
    load_stage(1, 1); cp_commit();

    for (int t = 0; t < T; t++) {
        int s = t % 3;
        cp_wait1();
        __syncthreads();
        if (t + 2 < T) load_stage(t + 2, (t + 2) % 3);
        cp_commit();   // one group per iteration (possibly empty) keeps accounting aligned

        const uint32_t* sa = (const uint32_t*)(smem + (size_t)s * STG);
        const uint32_t* sbp = (const uint32_t*)(smem + (size_t)s * STG + ASTAGE);
#pragma unroll
        for (int ks = 0; ks < 2; ks++) {
            uint32_t af[4][4], bf[8][2];
#pragma unroll
            for (int mt = 0; mt < 4; mt++) {
                const uint32_t* p = sa + (mW + mt * 16 + r) * LDSW + ks * 8 + cc;
                af[mt][0] = p[0];
                af[mt][1] = p[8 * LDSW];
                af[mt][2] = p[4];
                af[mt][3] = p[8 * LDSW + 4];
            }
#pragma unroll
            for (int nt = 0; nt < 8; nt++) {
                const uint32_t* q = sbp + (nW + nt * 8 + r) * LDSW + ks * 8 + cc;
                bf[nt][0] = q[0];
                bf[nt][1] = q[4];
            }
#pragma unroll
            for (int mt = 0; mt < 4; mt++)
#pragma unroll
                for (int nt = 0; nt < 8; nt++)
                    mma_tf32(acc[mt][nt], af[mt], bf[nt]);
        }
    }

    // epilogue: bias + activation (+round for intermediate layers)
    int gm = mBase + mW;
    int gn = nBase + nW;
#pragma unroll
    for (int nt = 0; nt < 8; nt++) {
        int c0 = gn + nt * 8 + 2 * cc;
        float b0 = bias[c0], b1v = bias[c0 + 1];
#pragma unroll
        for (int mt = 0; mt < 4; mt++) {
            int r0 = gm + mt * 16 + r;
            float v0 = acc[mt][nt][0] + b0;
            float v1 = acc[mt][nt][1] + b1v;
            float v2 = acc[mt][nt][2] + b0;
            float v3 = acc[mt][nt][3] + b1v;
            if (ACT == 1) {
                v0 = rtf(fmaxf(v0, 0.f)); v1 = rtf(fmaxf(v1, 0.f));
                v2 = rtf(fmaxf(v2, 0.f)); v3 = rtf(fmaxf(v3, 0.f));
            } else if (ACT == 2) {
                v0 = rtf(tanhf(v0)); v1 = rtf(tanhf(v1));
                v2 = rtf(tanhf(v2)); v3 = rtf(tanhf(v3));
            }
            *(float2*)&C[(size_t)r0 * Nn + c0] = make_float2(v0, v1);
            *(float2*)&C[(size_t)(r0 + 8) * Nn + c0] = make_float2(v2, v3);
        }
    }
}

// ---------------------------------------------------------------------------
extern "C" void kernel_launch(void* const* d_in, const int* in_sizes, int n_in,
                              void* d_out, int out_size) {
    const float* x  = (const float*)d_in[0];
    const float* Wg = (const float*)d_in[1];
    const float* We = (const float*)d_in[2];
    const float* be = (const float*)d_in[3];
    const float* W1 = (const float*)d_in[4];
    const float* b1 = (const float*)d_in[5];
    const float* W2 = (const float*)d_in[6];
    const float* b2 = (const float*)d_in[7];
    const float* Wo = (const float*)d_in[8];
    const float* bo = (const float*)d_in[9];
    float* out = (float*)d_out;

    cudaFuncSetAttribute(gemm_tf32_big<0>, cudaFuncAttributeMaxDynamicSharedMemorySize, SMEM_DYN);
    cudaFuncSetAttribute(gemm_tf32_big<1>, cudaFuncAttributeMaxDynamicSharedMemorySize, SMEM_DYN);
    cudaFuncSetAttribute(gemm_tf32_big<2>, cudaFuncAttributeMaxDynamicSharedMemorySize, SMEM_DYN);

    prep_kernel<<<(EDIM * DIM + 255) / 256, 256>>>(We, be, W1, W2, Wo);
    gate_kernel<<<NROWS, 128>>>(x, Wg);

    // he  = relu(gh @ WeT^T + bsum)   A=g_gh(0)  W=WeT(0)  C=g_bufA(1)
    gemm_tf32_big<1><<<dim3(EDIM / BN, NROWS / BM), 256, SMEM_DYN>>>(
        nullptr, nullptr, 0, 0, 1, EDIM, DIM);
    // o1  = tanh(he @ W1^T + b1)      A=g_bufA(1) W=W1r(1)  C=g_gh(0)
    gemm_tf32_big<2><<<dim3(EDIM / BN, NROWS / BM), 256, SMEM_DYN>>>(
        b1, nullptr, 1, 1, 0, EDIM, EDIM);
    // o2  = tanh(o1 @ W2^T + b2)      A=g_gh(0)  W=W2r(2)  C=g_bufA(1)
    gemm_tf32_big<2><<<dim3(EDIM / BN, NROWS / BM), 256, SMEM_DYN>>>(
        b2, nullptr, 0, 2, 1, EDIM, EDIM);
    // out = o2 @ Wo^T + bo            A=g_bufA(1) W=Wor(3)  C=out(2)
    gemm_tf32_big<0><<<dim3(ODIM / BN, NROWS / BM), 256, SMEM_DYN>>>(
        bo, out, 1, 3, 2, ODIM, EDIM);
}

// round 9
// speedup vs baseline: 1.1522x; 1.0346x over previous
#include <cuda_runtime.h>
#include <cstdint>

#define NROWS 32768      // B*T
#define DIM   1536       // L*IN
#define EDIM  1024
#define ODIM  512

// GEMM tiling: CTA 128x128, 8 warps of 64x32, 4-stage cp.async, 2 CTAs/SM
#define BM 128
#define BN 128
#define KT 16
#define LDSW 20                        // padded row stride in words (conflict-free)
#define ASTAGE (BM * LDSW * 4)         // 10240 B
#define BSTAGE (BN * LDSW * 4)         // 10240 B
#define STG (ASTAGE + BSTAGE)          // 20480 B
#define NSTAGES 4
#define SMEM_DYN (NSTAGES * STG)       // 81920 B per CTA

// ---------------- device-global scratch (no allocs) ----------------
__device__ float g_gh  [(size_t)NROWS * DIM];    // gated input; reused as o1 buffer
__device__ float g_bufA[(size_t)NROWS * EDIM];
__device__ float g_WeT [(size_t)EDIM * DIM];     // tf32-rounded transposed We
__device__ float g_W1r [(size_t)EDIM * EDIM];
__device__ float g_W2r [(size_t)EDIM * EDIM];
__device__ float g_Wor [(size_t)ODIM * EDIM];
__device__ float g_bsum[EDIM];

// ---------------- helpers ----------------
__device__ __forceinline__ uint32_t f2tf32(float f) {
    uint32_t u;
    asm("cvt.rna.tf32.f32 %0, %1;" : "=r"(u) : "f"(f));
    return u;
}
__device__ __forceinline__ float rtf(float f) { return __uint_as_float(f2tf32(f)); }

__device__ __forceinline__ uint32_t smem_u32(const void* p) {
    uint32_t a;
    asm("{ .reg .u64 t; cvta.to.shared.u64 t, %1; cvt.u32.u64 %0, t; }" : "=r"(a) : "l"(p));
    return a;
}
__device__ __forceinline__ void cp16(uint32_t dst, const void* src) {
    asm volatile("cp.async.cg.shared.global [%0], [%1], 16;" :: "r"(dst), "l"(src));
}
__device__ __forceinline__ void cp_commit() { asm volatile("cp.async.commit_group;" ::: "memory"); }
__device__ __forceinline__ void cp_wait2()  { asm volatile("cp.async.wait_group 2;" ::: "memory"); }

__device__ __forceinline__ void mma_tf32(float* c, const uint32_t* a, const uint32_t* b) {
    asm("mma.sync.aligned.m16n8k8.row.col.f32.tf32.tf32.f32 "
        "{%0,%1,%2,%3},{%4,%5,%6,%7},{%8,%9},{%0,%1,%2,%3};"
        : "+f"(c[0]), "+f"(c[1]), "+f"(c[2]), "+f"(c[3])
        : "r"(a[0]), "r"(a[1]), "r"(a[2]), "r"(a[3]),
          "r"(b[0]), "r"(b[1]));
}

// ---------------------------------------------------------------------------
// prep: WeT (tf32-rounded, transposed), rounded W copies, bias sum (fp32)
// ---------------------------------------------------------------------------
__global__ void prep_kernel(const float* __restrict__ We, const float* __restrict__ be,
                            const float* __restrict__ W1, const float* __restrict__ W2,
                            const float* __restrict__ Wo) {
    int idx = blockIdx.x * 256 + threadIdx.x;
    if (idx < EDIM * DIM) {
        int e = idx / DIM, k = idx - e * DIM;
        int l = k >> 9, i = k & 511;
        g_WeT[idx] = rtf(We[((size_t)l * EDIM + e) * 512 + i]);
    }
    if (idx < EDIM * EDIM) {
        g_W1r[idx] = rtf(W1[idx]);
        g_W2r[idx] = rtf(W2[idx]);
    }
    if (idx < ODIM * EDIM) g_Wor[idx] = rtf(Wo[idx]);
    if (idx < EDIM) g_bsum[idx] = be[idx] + be[EDIM + idx] + be[2 * EDIM + idx];
}

// ---------------------------------------------------------------------------
// gates: g[n,l] = sigmoid(x[n,:].Wg[l,:]); gh[n,k] = rtf(x[n,k]*g[n,k/512])
// ---------------------------------------------------------------------------
__global__ void gate_kernel(const float* __restrict__ x, const float* __restrict__ Wgt) {
    int n = blockIdx.x;
    int tid = threadIdx.x;
    const float* xr = x + (size_t)n * DIM;
    float xv[12];
    float a0 = 0.f, a1 = 0.f, a2 = 0.f;
#pragma unroll
    for (int j = 0; j < 12; j++) {
        int k = tid + j * 128;
        float v = xr[k];
        xv[j] = v;
        a0 += v * Wgt[k];
        a1 += v * Wgt[DIM + k];
        a2 += v * Wgt[2 * DIM + k];
    }
#pragma unroll
    for (int o = 16; o > 0; o >>= 1) {
        a0 += __shfl_down_sync(0xffffffffu, a0, o);
        a1 += __shfl_down_sync(0xffffffffu, a1, o);
        a2 += __shfl_down_sync(0xffffffffu, a2, o);
    }
    __shared__ float red[3][4];
    __shared__ float gs[3];
    int lane = tid & 31, wid = tid >> 5;
    if (lane == 0) { red[0][wid] = a0; red[1][wid] = a1; red[2][wid] = a2; }
    __syncthreads();
    if (tid < 3) {
        float s = red[tid][0] + red[tid][1] + red[tid][2] + red[tid][3];
        gs[tid] = 1.f / (1.f + expf(-s));
    }
    __syncthreads();
    float g0 = gs[0], g1 = gs[1], g2 = gs[2];
    float* o = g_gh + (size_t)n * DIM;
#pragma unroll
    for (int j = 0; j < 12; j++) {
        int k = tid + j * 128;
        float gl = (j < 4) ? g0 : ((j < 8) ? g1 : g2);
        o[k] = rtf(xv[j] * gl);
    }
}

// ---------------------------------------------------------------------------
// TF32 GEMM (legacy mma.sync): C = act(A @ W^T + bias)
// CTA 128x128, 8 warps at 64x32 (2M x 4N), K-tile 16, 4-stage cp.async,
// __launch_bounds__(256, 2) -> <=128 regs -> 2 CTAs/SM (16 warps/SM).
// Inputs pre-rounded tf32. ACT: 0 none, 1 relu+round, 2 tanh+round.
// ---------------------------------------------------------------------------
template <int ACT>
__global__ void __launch_bounds__(256, 2) gemm_tf32_p2(
    const float* __restrict__ biasE, float* __restrict__ Cext,
    int aSel, int wSel, int cSel, int Nn, int K) {
    extern __shared__ char smem[];
    uint32_t sb = smem_u32(smem);

    const float* A = (aSel == 0) ? g_gh : g_bufA;
    const float* W = (wSel == 0) ? g_WeT : (wSel == 1) ? g_W1r : (wSel == 2) ? g_W2r : g_Wor;
    const float* bias = (wSel == 0) ? g_bsum : biasE;
    float* C = (cSel == 0) ? g_gh : (cSel == 1) ? g_bufA : Cext;

    int tid = threadIdx.x;
    int lane = tid & 31, warp = tid >> 5;
    int wm = warp & 1, wn = warp >> 1;    // 2 warps along M (64), 4 along N (32)
    int mW = wm * 64, nW = wn * 32;
    int r = lane >> 2, cc = lane & 3;

    int mBase = blockIdx.y * BM;
    int nBase = blockIdx.x * BN;
    const float* Ag = A + (size_t)mBase * K;
    const float* Wg = W + (size_t)nBase * K;

    int arow = tid >> 2;              // 0..63
    int c4 = (tid & 3) * 4;           // k word offset 0/4/8/12

    auto load_stage = [&](int kt, int s) {
        uint32_t ab = sb + (uint32_t)s * STG;
        uint32_t bb = ab + ASTAGE;
        size_t ko = (size_t)kt * KT + c4;
#pragma unroll
        for (int j = 0; j < 2; j++) {
            int row = arow + j * 64;
            cp16(ab + (uint32_t)(row * LDSW + c4) * 4, Ag + (size_t)row * K + ko);
            cp16(bb + (uint32_t)(row * LDSW + c4) * 4, Wg + (size_t)row * K + ko);
        }
    };

    float acc[4][4][4];
#pragma unroll
    for (int i = 0; i < 4; i++)
#pragma unroll
        for (int j = 0; j < 4; j++)
#pragma unroll
            for (int k = 0; k < 4; k++) acc[i][j][k] = 0.f;

    int T = K / KT;
    load_stage(0, 0); cp_commit();
    load_stage(1, 1); cp_commit();
    load_stage(2, 2); cp_commit();

    for (int t = 0; t < T; t++) {
        int s = t & 3;
        cp_wait2();
        __syncthreads();
        if (t + 3 < T) load_stage(t + 3, (t + 3) & 3);
        cp_commit();   // one group per iteration keeps accounting aligned

        const uint32_t* sa  = (const uint32_t*)(smem + (size_t)s * STG);
        const uint32_t* sbp = (const uint32_t*)(smem + (size_t)s * STG + ASTAGE);
#pragma unroll
        for (int ks = 0; ks < 2; ks++) {
            uint32_t af[4][4], bf[4][2];
#pragma unroll
            for (int mt = 0; mt < 4; mt++) {
                const uint32_t* p = sa + (mW + mt * 16 + r) * LDSW + ks * 8 + cc;
                af[mt][0] = p[0];
                af[mt][1] = p[8 * LDSW];
                af[mt][2] = p[4];
                af[mt][3] = p[8 * LDSW + 4];
            }
#pragma unroll
            for (int nt = 0; nt < 4; nt++) {
                const uint32_t* q = sbp + (nW + nt * 8 + r) * LDSW + ks * 8 + cc;
                bf[nt][0] = q[0];
                bf[nt][1] = q[4];
            }
#pragma unroll
            for (int mt = 0; mt < 4; mt++)
#pragma unroll
                for (int nt = 0; nt < 4; nt++)
                    mma_tf32(acc[mt][nt], af[mt], bf[nt]);
        }
    }

    // epilogue: bias + activation (+round for intermediate layers)
    int gm = mBase + mW;
    int gn = nBase + nW;
#pragma unroll
    for (int nt = 0; nt < 4; nt++) {
        int c0 = gn + nt * 8 + 2 * cc;
        float b0 = bias[c0], b1v = bias[c0 + 1];
#pragma unroll
        for (int mt = 0; mt < 4; mt++) {
            int r0 = gm + mt * 16 + r;
            float v0 = acc[mt][nt][0] + b0;
            float v1 = acc[mt][nt][1] + b1v;
            float v2 = acc[mt][nt][2] + b0;
            float v3 = acc[mt][nt][3] + b1v;
            if (ACT == 1) {
                v0 = rtf(fmaxf(v0, 0.f)); v1 = rtf(fmaxf(v1, 0.f));
                v2 = rtf(fmaxf(v2, 0.f)); v3 = rtf(fmaxf(v3, 0.f));
            } else if (ACT == 2) {
                v0 = rtf(tanhf(v0)); v1 = rtf(tanhf(v1));
                v2 = rtf(tanhf(v2)); v3 = rtf(tanhf(v3));
            }
            *(float2*)&C[(size_t)r0 * Nn + c0] = make_float2(v0, v1);
            *(float2*)&C[(size_t)(r0 + 8) * Nn + c0] = make_float2(v2, v3);
        }
    }
}

// ---------------------------------------------------------------------------
extern "C" void kernel_launch(void* const* d_in, const int* in_sizes, int n_in,
                              void* d_out, int out_size) {
    const float* x  = (const float*)d_in[0];
    const float* Wg = (const float*)d_in[1];
    const float* We = (const float*)d_in[2];
    const float* be = (const float*)d_in[3];
    const float* W1 = (const float*)d_in[4];
    const float* b1 = (const float*)d_in[5];
    const float* W2 = (const float*)d_in[6];
    const float* b2 = (const float*)d_in[7];
    const float* Wo = (const float*)d_in[8];
    const float* bo = (const float*)d_in[9];
    float* out = (float*)d_out;

    cudaFuncSetAttribute(gemm_tf32_p2<0>, cudaFuncAttributeMaxDynamicSharedMemorySize, SMEM_DYN);
    cudaFuncSetAttribute(gemm_tf32_p2<1>, cudaFuncAttributeMaxDynamicSharedMemorySize, SMEM_DYN);
    cudaFuncSetAttribute(gemm_tf32_p2<2>, cudaFuncAttributeMaxDynamicSharedMemorySize, SMEM_DYN);

    prep_kernel<<<(EDIM * DIM + 255) / 256, 256>>>(We, be, W1, W2, Wo);
    gate_kernel<<<NROWS, 128>>>(x, Wg);

    // he  = relu(gh @ WeT^T + bsum)   A=g_gh(0)  W=WeT(0)  C=g_bufA(1)
    gemm_tf32_p2<1><<<dim3(EDIM / BN, NROWS / BM), 256, SMEM_DYN>>>(
        nullptr, nullptr, 0, 0, 1, EDIM, DIM);
    // o1  = tanh(he @ W1^T + b1)      A=g_bufA(1) W=W1r(1)  C=g_gh(0)
    gemm_tf32_p2<2><<<dim3(EDIM / BN, NROWS / BM), 256, SMEM_DYN>>>(
        b1, nullptr, 1, 1, 0, EDIM, EDIM);
    // o2  = tanh(o1 @ W2^T + b2)      A=g_gh(0)  W=W2r(2)  C=g_bufA(1)
    gemm_tf32_p2<2><<<dim3(EDIM / BN, NROWS / BM), 256, SMEM_DYN>>>(
        b2, nullptr, 0, 2, 1, EDIM, EDIM);
    // out = o2 @ Wo^T + bo            A=g_bufA(1) W=Wor(3)  C=out(2)
    gemm_tf32_p2<0><<<dim3(ODIM / BN, NROWS / BM), 256, SMEM_DYN>>>(
        bo, out, 1, 3, 2, ODIM, EDIM);
}